// round 16
// baseline (speedup 1.0000x reference)
#include <cuda_runtime.h>
#include <cstdint>
#include <math.h>

#define BB 16
#define CC 256
#define HH 128
#define WW 128
#define HW 16384
#define MM 32
#define NMODE 1024
#define TD 512
#define CD 512
#define NG 8
#define EPSV 1e-5f

typedef unsigned long long u64;

// ---------------- persistent scratch ----------------
__device__ float2 g_A[(size_t)BB*CC*HH*MM];      // reused as kC half-1 output
__device__ float2 g_Smode[(size_t)BB*CC*NMODE];
__device__ float2 g_Omode[(size_t)BB*CC*NMODE];  // kC half-0 output
__device__ float  g_h[(size_t)BB*CC*HW];
__device__ float  g_tvec[BB*CC];
__device__ float  g_scale[BB*CC];
__device__ float  g_shift[BB*CC];
__device__ float  g_stats[BB*NG*2];
__device__ float2 g_tabJK[HH*MM];
__device__ float2 g_tabKJ[MM*HH];

// ---------------- helpers ----------------
__device__ __forceinline__ uint32_t smem_u32(const void* p) {
    return (uint32_t)__cvta_generic_to_shared(p);
}
__device__ __forceinline__ void cpasync16(uint32_t dst, const void* src) {
    asm volatile("cp.async.ca.shared.global [%0], [%1], 16;" :: "r"(dst), "l"(src));
}
__device__ __forceinline__ void cpcommit() { asm volatile("cp.async.commit_group;"); }
template<int N>
__device__ __forceinline__ void cpwait() { asm volatile("cp.async.wait_group %0;" :: "n"(N)); }
__device__ __forceinline__ uint32_t f2tf(float v) { return __float_as_uint(v); }
__device__ __forceinline__ float tf32r(float v) {
    uint32_t r;
    asm("cvt.rna.tf32.f32 %0, %1;" : "=r"(r) : "f"(v));
    return __uint_as_float(r);
}
__device__ __forceinline__ void mma_tf32(float* d, const uint32_t* a, const uint32_t* b) {
    asm volatile("mma.sync.aligned.m16n8k8.row.col.f32.tf32.tf32.f32 "
                 "{%0,%1,%2,%3}, {%4,%5,%6,%7}, {%8,%9}, {%0,%1,%2,%3};"
                 : "+f"(d[0]), "+f"(d[1]), "+f"(d[2]), "+f"(d[3])
                 : "r"(a[0]), "r"(a[1]), "r"(a[2]), "r"(a[3]), "r"(b[0]), "r"(b[1]));
}
__device__ __forceinline__ u64 pack2(float x, float y) {
    u64 r; asm("mov.b64 %0, {%1, %2};" : "=l"(r) : "f"(x), "f"(y)); return r;
}
__device__ __forceinline__ u64 fma2(u64 a, u64 b, u64 c) {
    u64 d; asm("fma.rn.f32x2 %0, %1, %2, %3;" : "=l"(d) : "l"(a), "l"(b), "l"(c)); return d;
}
__device__ __forceinline__ u64 neg2(u64 a) { return a ^ 0x8000000080000000ULL; }
__device__ __forceinline__ float2 unpack2(u64 a) {
    float2 v; asm("mov.b64 {%0, %1}, %2;" : "=f"(v.x), "=f"(v.y) : "l"(a)); return v;
}

// ---------------- K0: tables + embedding projections (parallelized) ----------------
__global__ void k0_prep(const float* __restrict__ t_emb, const float* __restrict__ cond_emb,
                        const float* __restrict__ tp_w, const float* __restrict__ tp_b,
                        const float* __restrict__ cp_w, const float* __restrict__ cp_b) {
    int t = threadIdx.x;
    if (blockIdx.x == 128) {
        for (int e = t; e < HH*MM; e += 256) {
            int j = e >> 5, k = e & 31;
            float ang = (float)((j * k) & 127) * 0.049087385212340517f;
            float s, c; sincosf(ang, &s, &c);
            g_tabJK[j*MM + k] = make_float2(c, s);
            g_tabKJ[k*HH + j] = make_float2(c, s);
        }
        if (t < BB*NG*2) g_stats[t] = 0.f;
        return;
    }
    int b = blockIdx.x >> 3;
    int cg = blockIdx.x & 7;
    __shared__ float st[TD];
    __shared__ float sc[CD];
    __shared__ float red[3][32][9];
    for (int e = t; e < TD; e += 256) { float v = t_emb[b*TD + e];   st[e] = v / (1.f + expf(-v)); }
    for (int e = t; e < CD; e += 256) { float v = cond_emb[b*CD + e]; sc[e] = v / (1.f + expf(-v)); }
    __syncthreads();
    int cl = t & 31, sl = t >> 5;
    int c = cg*32 + cl;
    float tv = 0.f, s1 = 0.f, s2 = 0.f;
    const float* tw = tp_w + (size_t)c*TD + sl*64;
    const float* c1 = cp_w + (size_t)c*CD + sl*64;
    const float* c2 = cp_w + (size_t)(c + CC)*CD + sl*64;
    #pragma unroll 4
    for (int d = 0; d < 64; d++) tv = fmaf(st[sl*64 + d], tw[d], tv);
    #pragma unroll 4
    for (int d = 0; d < 64; d++) { s1 = fmaf(sc[sl*64 + d], c1[d], s1); s2 = fmaf(sc[sl*64 + d], c2[d], s2); }
    red[0][cl][sl] = tv; red[1][cl][sl] = s1; red[2][cl][sl] = s2;
    __syncthreads();
    if (t < 32) {
        float a0 = 0.f, a1 = 0.f, a2 = 0.f;
        #pragma unroll
        for (int s = 0; s < 8; s++) { a0 += red[0][t][s]; a1 += red[1][t][s]; a2 += red[2][t][s]; }
        int cc = cg*32 + t;
        g_tvec[b*CC + cc]  = a0 + tp_b[cc];
        g_scale[b*CC + cc] = a1 + cp_b[cc];
        g_shift[b*CC + cc] = a2 + cp_b[cc + CC];
    }
}

// ---------------- kAB: fused forward DFT, BOTH phases as tf32 mma ----------------
#define TSA_(k,n)      sdyn[(k)*68 + (n)]
#define XSA_(st,r,k)   sdyn[8704 + (st)*4608 + (r)*36 + (k)]
#define AT2_(ky,c)     sdyn[(ky)*260 + (c)]
#define TB2_(k,c)      sdyn[8320 + (k)*72 + (c)]

__global__ void __launch_bounds__(256, 2) kAB_fused(const float* __restrict__ x) {
    extern __shared__ float sdyn[];
    int t = threadIdx.x, lane = t & 31, warp = t >> 5;
    int wm = warp >> 1, wn = warp & 1;
    int bc = blockIdx.x;
    int R0 = bc * 128;

    for (int e = t; e < HH*MM; e += 256) {
        int m = e >> 5, ky = e & 31;
        float2 cs = g_tabJK[e];
        TSA_(m, 2*ky)     = cs.x;
        TSA_(m, 2*ky + 1) = -cs.y;
    }
    #pragma unroll
    for (int q = 0; q < 4; q++) {
        int idx = t + 256*q;
        int row = idx >> 3, c4 = idx & 7;
        cpasync16(smem_u32(&XSA_(0, row, c4*4)), x + (size_t)(R0 + row)*128 + c4*4);
    }
    cpcommit();

    float acc[2][4][4];
    #pragma unroll
    for (int mf = 0; mf < 2; mf++)
        #pragma unroll
        for (int nf = 0; nf < 4; nf++)
            #pragma unroll
            for (int e = 0; e < 4; e++) acc[mf][nf][e] = 0.f;

    for (int kc = 0; kc < 4; kc++) {
        if (kc + 1 < 4) {
            int k0 = (kc + 1) * 32, st2 = (kc + 1) & 1;
            #pragma unroll
            for (int q = 0; q < 4; q++) {
                int idx = t + 256*q;
                int row = idx >> 3, c4 = idx & 7;
                cpasync16(smem_u32(&XSA_(st2, row, c4*4)), x + (size_t)(R0 + row)*128 + k0 + c4*4);
            }
            cpcommit();
            cpwait<1>();
        } else {
            cpwait<0>();
        }
        __syncthreads();
        int st = kc & 1;
        #pragma unroll
        for (int k8 = 0; k8 < 4; k8++) {
            uint32_t a[2][4], b[4][2];
            int arow = wm*32 + (lane >> 2);
            int acol = (lane & 3) + k8*8;
            #pragma unroll
            for (int mf = 0; mf < 2; mf++) {
                int r = arow + mf*16;
                a[mf][0] = f2tf(XSA_(st, r,     acol));
                a[mf][1] = f2tf(XSA_(st, r + 8, acol));
                a[mf][2] = f2tf(XSA_(st, r,     acol + 4));
                a[mf][3] = f2tf(XSA_(st, r + 8, acol + 4));
            }
            int kg = kc*32 + k8*8 + (lane & 3);
            int bn0 = wn*32 + (lane >> 2);
            #pragma unroll
            for (int nf = 0; nf < 4; nf++) {
                b[nf][0] = f2tf(TSA_(kg,     bn0 + nf*8));
                b[nf][1] = f2tf(TSA_(kg + 4, bn0 + nf*8));
            }
            #pragma unroll
            for (int mf = 0; mf < 2; mf++)
                #pragma unroll
                for (int nf = 0; nf < 4; nf++)
                    mma_tf32(acc[mf][nf], a[mf], b[nf]);
        }
        __syncthreads();
    }

    #pragma unroll
    for (int mf = 0; mf < 2; mf++) {
        int r = wm*32 + mf*16 + (lane >> 2);
        #pragma unroll
        for (int nf = 0; nf < 4; nf++) {
            int ky = wn*16 + nf*4 + (lane & 3);
            *(float2*)&AT2_(ky, 2*r)       = make_float2(acc[mf][nf][0], acc[mf][nf][1]);
            *(float2*)&AT2_(ky, 2*(r + 8)) = make_float2(acc[mf][nf][2], acc[mf][nf][3]);
        }
    }
    for (int e = t; e < 16384; e += 256) {
        int row = e >> 6, colc = e & 63;
        int n = row >> 1, u = row & 1;
        int kx = colc >> 1, v = colc & 1;
        float2 cs = g_tabJK[n*32 + kx];
        float val = u ? (v ? cs.x : cs.y) : (v ? -cs.y : cs.x);
        TB2_(row, colc) = val * (1.f/128.f);
    }
    __syncthreads();

    {
        int wm2 = warp >> 2, wn2 = warp & 3;
        float acc2[2][4];
        #pragma unroll
        for (int nf = 0; nf < 2; nf++)
            #pragma unroll
            for (int e = 0; e < 4; e++) acc2[nf][e] = 0.f;

        int r2 = wm2*16 + (lane >> 2);
        int n2 = wn2*16 + (lane >> 2);
        #pragma unroll
        for (int k8 = 0; k8 < 32; k8++) {
            uint32_t a[4], b[2][2];
            int kk = (lane & 3) + k8*8;
            a[0] = f2tf(AT2_(r2,     kk));
            a[1] = f2tf(AT2_(r2 + 8, kk));
            a[2] = f2tf(AT2_(r2,     kk + 4));
            a[3] = f2tf(AT2_(r2 + 8, kk + 4));
            #pragma unroll
            for (int nf = 0; nf < 2; nf++) {
                b[nf][0] = f2tf(TB2_(kk,     n2 + nf*8));
                b[nf][1] = f2tf(TB2_(kk + 4, n2 + nf*8));
            }
            #pragma unroll
            for (int nf = 0; nf < 2; nf++)
                mma_tf32(acc2[nf], a, b[nf]);
        }

        float* So = (float*)g_Smode + (size_t)bc*2048;
        int ky0 = r2, ky1 = r2 + 8;
        int off0 = (ky0 >> 1)*4 + (ky0 & 1);
        int off1 = (ky1 >> 1)*4 + (ky1 & 1);
        #pragma unroll
        for (int nf = 0; nf < 2; nf++) {
            int kx = wn2*8 + (lane & 3) + nf*4;
            float* dst = So + kx*64;
            dst[off0]     = acc2[nf][0];
            dst[off0 + 2] = acc2[nf][1];
            dst[off1]     = acc2[nf][2];
            dst[off1 + 2] = acc2[nf][3];
        }
    }
}

// ---------------- kC: channel mix, split-K 2, 6-stage pipeline ----------------
#define SS6(st,b,f)    sdyn[(st) + (b)*64 + (f)]
#define WS6(st,h,o,f)  sdyn[6144 + (st) + (h)*512 + (o)*32 + (f)]

__global__ void __launch_bounds__(256, 2) kC_mix6(const float* __restrict__ w_real,
                                                  const float* __restrict__ w_imag) {
    extern __shared__ float sdyn[];
    int t = threadIdx.x;
    int ih = blockIdx.x >> 9;
    int kx = (blockIdx.x >> 4) & 31;
    int o0 = (blockIdx.x & 15) << 4;
    int i0 = ih << 7;
    const int NI = 128;

    int sb = t >> 4, sf = t & 15;
    const float* wsrc = (t < 128) ? w_real : w_imag;
    int whalf = t >> 7, wo = (t >> 3) & 15, wf = t & 7;

    int kyp = t & 15, bq = (t >> 4) & 3, oq = t >> 6;

    u64 ar[4][4], ai[4][4];
    #pragma unroll
    for (int b4 = 0; b4 < 4; b4++)
        #pragma unroll
        for (int o4 = 0; o4 < 4; o4++) { ar[b4][o4] = 0ULL; ai[b4][o4] = 0ULL; }

    const float* sPtr = (const float*)g_Smode + (size_t)(sb*CC + i0)*2048 + kx*64 + sf*4;
    const float* wPtr = wsrc + ((size_t)(i0*CC + o0 + wo) << 10) + (kx << 5) + wf*4;
    uint32_t sDst = smem_u32(&SS6(0, sb, sf*4));
    uint32_t wDst = smem_u32(&WS6(0, whalf, wo, wf*4));

    #pragma unroll
    for (int i = 0; i < 5; i++) {
        cpasync16(sDst + i*4096, sPtr);  sPtr += 2048;
        cpasync16(wDst + i*4096, wPtr);  wPtr += (size_t)CC << 10;
        cpcommit();
    }

    int stc = 0;
    int stp = 5*1024;
    uint32_t sPD = sDst + 5*4096, wPD = wDst + 5*4096;

    for (int i = 0; i < NI; i++) {
        cpwait<4>();
        __syncthreads();
        if (i + 5 < NI) {
            cpasync16(sPD, sPtr);  sPtr += 2048;
            cpasync16(wPD, wPtr);  wPtr += (size_t)CC << 10;
        }
        cpcommit();
        sPD += 4096; wPD += 4096;
        if (stp == 5*1024) { sPD -= 6*4096; wPD -= 6*4096; stp = 0; } else stp += 1024;

        int st = stc;
        u64 sx[4], sy[4], nsy[4];
        #pragma unroll
        for (int b4 = 0; b4 < 4; b4++) {
            int b = 4*b4 + bq;
            sx[b4]  = *(u64*)&SS6(st, b, 4*kyp);
            sy[b4]  = *(u64*)&SS6(st, b, 4*kyp + 2);
            nsy[b4] = neg2(sy[b4]);
        }
        #pragma unroll
        for (int o4 = 0; o4 < 4; o4++) {
            int ow = 4*o4 + oq;
            u64 wr = *(u64*)&WS6(st, 0, ow, 2*kyp);
            u64 wi = *(u64*)&WS6(st, 1, ow, 2*kyp);
            #pragma unroll
            for (int b4 = 0; b4 < 4; b4++) {
                ar[b4][o4] = fma2(sx[b4], wr, fma2(nsy[b4], wi, ar[b4][o4]));
                ai[b4][o4] = fma2(sx[b4], wi, fma2(sy[b4],  wr, ai[b4][o4]));
            }
        }
        stc = (stc == 5*1024) ? 0 : stc + 1024;
    }
    float* OmF = ih ? (float*)g_A : (float*)g_Omode;
    #pragma unroll
    for (int b4 = 0; b4 < 4; b4++) {
        int b = 4*b4 + bq;
        #pragma unroll
        for (int o4 = 0; o4 < 4; o4++) {
            int o = o0 + 4*o4 + oq;
            float* dst = OmF + (size_t)(b*CC + o)*2048 + kx*64;
            *(float2*)&dst[2*kyp]      = unpack2(ar[b4][o4]);
            *(float2*)&dst[32 + 2*kyp] = unpack2(ai[b4][o4]);
        }
    }
}

// ---------------- kDE: inverse DFTs as tf32 mma, n-split (2 CTAs per bo, occ 3) ----------------
// smem: USE [64][132] @0 (8448), GSE [64][68] @8448 (4352), B1 [64][68] @12800 (4352) = 17152 floats
#define USE_(k,n)   sdyn[(k)*132 + (n)]
#define GSE_(r,k)   sdyn[8448 + (r)*68 + (k)]
#define B1_(k,c)    sdyn[12800 + (k)*68 + (c)]

__global__ void __launch_bounds__(256, 3) kDE_fused() {
    extern __shared__ float sdyn[];
    int t = threadIdx.x, lane = t & 31, warp = t >> 5;
    int wm = warp >> 1, wn = warp & 1;
    int bo = blockIdx.x >> 1;
    int nh = blockIdx.x & 1;      // which 64-row half of n

    for (int e = t; e < MM*HH; e += 256) {
        int ky = e >> 7, m = e & 127;
        float2 cs = g_tabKJ[e];
        USE_(2*ky,     m) = cs.x;
        USE_(2*ky + 1, m) = -cs.y;
    }
    {
        int kx = t >> 3, g = t & 7;
        const float* s1 = (const float*)g_Omode + (size_t)bo*2048 + kx*64;
        const float* s2 = (const float*)g_A + (size_t)bo*2048 + kx*64;
        float4 or1 = *(const float4*)&s1[g*4];
        float4 or2 = *(const float4*)&s2[g*4];
        float4 oi1 = *(const float4*)&s1[32 + g*4];
        float4 oi2 = *(const float4*)&s2[32 + g*4];
        float Or[4] = {or1.x + or2.x, or1.y + or2.y, or1.z + or2.z, or1.w + or2.w};
        float Oi[4] = {oi1.x + oi2.x, oi1.y + oi2.y, oi1.z + oi2.z, oi1.w + oi2.w};
        #pragma unroll
        for (int j = 0; j < 4; j++) {
            int ky = g*4 + j;
            float fac = (ky == 0 ? 1.f : 2.f) * (1.f/128.f);
            float fr = tf32r(Or[j]*fac), fi = tf32r(Oi[j]*fac);
            *(float2*)&B1_(2*kx,     2*ky) = make_float2(fr, fi);
            *(float2*)&B1_(2*kx + 1, 2*ky) = make_float2(fi, -fr);
        }
    }
    __syncthreads();

    // ---- phase 1: G rows [nh*64, nh*64+64) = USE^T(rows) @ B1 ----
    {
        float acc1[4][4];
        #pragma unroll
        for (int nf = 0; nf < 4; nf++)
            #pragma unroll
            for (int e = 0; e < 4; e++) acc1[nf][e] = 0.f;

        int rloc = wm*16 + (lane >> 2);           // local row 0..63
        int rglob = nh*64 + rloc;                 // global n
        #pragma unroll
        for (int k8 = 0; k8 < 8; k8++) {
            uint32_t a[4], b[4][2];
            int k = (lane & 3) + k8*8;
            a[0] = f2tf(USE_(k,     rglob));
            a[1] = f2tf(USE_(k,     rglob + 8));
            a[2] = f2tf(USE_(k + 4, rglob));
            a[3] = f2tf(USE_(k + 4, rglob + 8));
            int col0 = wn*32 + (lane >> 2);
            #pragma unroll
            for (int nf = 0; nf < 4; nf++) {
                b[nf][0] = f2tf(B1_(k,     col0 + nf*8));
                b[nf][1] = f2tf(B1_(k + 4, col0 + nf*8));
            }
            #pragma unroll
            for (int nf = 0; nf < 4; nf++)
                mma_tf32(acc1[nf], a, b[nf]);
        }
        __syncthreads();   // B1 reads done everywhere before GSE writes? (separate regions, but keep ordering cheap)
        #pragma unroll
        for (int nf = 0; nf < 4; nf++) {
            int col = wn*32 + nf*8 + 2*(lane & 3);
            *(float2*)&GSE_(rloc,     col) = make_float2(acc1[nf][0], acc1[nf][1]);
            *(float2*)&GSE_(rloc + 8, col) = make_float2(acc1[nf][2], acc1[nf][3]);
        }
    }
    __syncthreads();

    // ---- phase 2: h rows = GSE[64x64] @ USE[64x128] ----
    float acc[8][4];
    #pragma unroll
    for (int nf = 0; nf < 8; nf++)
        #pragma unroll
        for (int e = 0; e < 4; e++) acc[nf][e] = 0.f;

    int rloc = wm*16 + (lane >> 2);
    #pragma unroll
    for (int k8 = 0; k8 < 8; k8++) {
        uint32_t a[4], b[8][2];
        int acol = (lane & 3) + k8*8;
        a[0] = f2tf(GSE_(rloc,     acol));
        a[1] = f2tf(GSE_(rloc + 8, acol));
        a[2] = f2tf(GSE_(rloc,     acol + 4));
        a[3] = f2tf(GSE_(rloc + 8, acol + 4));
        int kg = k8*8 + (lane & 3);
        int bn0 = wn*64 + (lane >> 2);
        #pragma unroll
        for (int nf = 0; nf < 8; nf++) {
            b[nf][0] = f2tf(USE_(kg,     bn0 + nf*8));
            b[nf][1] = f2tf(USE_(kg + 4, bn0 + nf*8));
        }
        #pragma unroll
        for (int nf = 0; nf < 8; nf++)
            mma_tf32(acc[nf], a, b[nf]);
    }

    int rbase = bo*128 + nh*64 + rloc;
    #pragma unroll
    for (int nf = 0; nf < 8; nf++) {
        int col = wn*64 + nf*8 + 2*(lane & 3);
        *(float2*)&g_h[(size_t)rbase*128 + col]       = make_float2(acc[nf][0], acc[nf][1]);
        *(float2*)&g_h[(size_t)(rbase + 8)*128 + col] = make_float2(acc[nf][2], acc[nf][3]);
    }
}

// ---------------- kF: pointwise GEMM via tf32 mma + fused epilogue + GN stats ----------------
#define ASM_(st,r,c) sdyn[(st)*4608 + (r)*36 + (c)]
#define BSM_(st,k,n) sdyn[9216 + (st)*4352 + (k)*136 + (n)]

__global__ void __launch_bounds__(256, 2) kF_mma(const float* __restrict__ x,
                                                 const float* __restrict__ pw_w,
                                                 const float* __restrict__ pw_b) {
    extern __shared__ float sdyn[];
    int t = threadIdx.x;
    int lane = t & 31, warp = t >> 5;
    int wm = warp >> 1, wn = warp & 1;
    int bi = blockIdx.x;
    int bb = bi >> 8;
    int ot = (bi >> 7) & 1, hwt = bi & 127;
    int o0 = ot * 128, hw0 = hwt * 128;

    float acc[2][8][4];
    #pragma unroll
    for (int mf = 0; mf < 2; mf++)
        #pragma unroll
        for (int nf = 0; nf < 8; nf++)
            #pragma unroll
            for (int e = 0; e < 4; e++) acc[mf][nf][e] = 0.f;

    {
        int i0 = 0;
        #pragma unroll
        for (int q = 0; q < 4; q++) {
            int idx = t + 256*q;
            int row = idx >> 3, c4 = idx & 7;
            cpasync16(smem_u32(&ASM_(0, row, c4*4)), pw_w + (size_t)(o0 + row)*CC + i0 + c4*4);
        }
        #pragma unroll
        for (int q = 0; q < 4; q++) {
            int idx = t + 256*q;
            int row = idx >> 5, c4 = idx & 31;
            cpasync16(smem_u32(&BSM_(0, row, c4*4)),
                      x + (((size_t)(bb*CC + i0 + row)) << 14) + hw0 + c4*4);
        }
        cpcommit();
    }

    for (int kc = 0; kc < 8; kc++) {
        if (kc + 1 < 8) {
            int i0 = (kc + 1) * 32, st2 = (kc + 1) & 1;
            #pragma unroll
            for (int q = 0; q < 4; q++) {
                int idx = t + 256*q;
                int row = idx >> 3, c4 = idx & 7;
                cpasync16(smem_u32(&ASM_(st2, row, c4*4)), pw_w + (size_t)(o0 + row)*CC + i0 + c4*4);
            }
            #pragma unroll
            for (int q = 0; q < 4; q++) {
                int idx = t + 256*q;
                int row = idx >> 5, c4 = idx & 31;
                cpasync16(smem_u32(&BSM_(st2, row, c4*4)),
                          x + (((size_t)(bb*CC + i0 + row)) << 14) + hw0 + c4*4);
            }
            cpcommit();
            cpwait<1>();
        } else {
            cpwait<0>();
        }
        __syncthreads();
        int st = kc & 1;
        #pragma unroll
        for (int k8 = 0; k8 < 4; k8++) {
            uint32_t a[2][4], b[8][2];
            int arow = wm*32 + (lane >> 2);
            int acol = (lane & 3) + k8*8;
            #pragma unroll
            for (int mf = 0; mf < 2; mf++) {
                int r = arow + mf*16;
                a[mf][0] = f2tf(ASM_(st, r,     acol));
                a[mf][1] = f2tf(ASM_(st, r + 8, acol));
                a[mf][2] = f2tf(ASM_(st, r,     acol + 4));
                a[mf][3] = f2tf(ASM_(st, r + 8, acol + 4));
            }
            int bk = (lane & 3) + k8*8;
            int bn0 = wn*64 + (lane >> 2);
            #pragma unroll
            for (int nf = 0; nf < 8; nf++) {
                b[nf][0] = f2tf(BSM_(st, bk,     bn0 + nf*8));
                b[nf][1] = f2tf(BSM_(st, bk + 4, bn0 + nf*8));
            }
            #pragma unroll
            for (int mf = 0; mf < 2; mf++)
                #pragma unroll
                for (int nf = 0; nf < 8; nf++)
                    mma_tf32(acc[mf][nf], a[mf], b[nf]);
        }
        __syncthreads();
    }

    float lsum = 0.f, lsum2 = 0.f;
    #pragma unroll
    for (int mf = 0; mf < 2; mf++) {
        int rbase = o0 + wm*32 + mf*16 + (lane >> 2);
        float addb[2], scl[2], shf[2];
        #pragma unroll
        for (int h = 0; h < 2; h++) {
            int o = rbase + 8*h;
            addb[h] = pw_b[o] + g_tvec[bb*CC + o];
            scl[h]  = 1.f + g_scale[bb*CC + o];
            shf[h]  = g_shift[bb*CC + o];
        }
        #pragma unroll
        for (int nf = 0; nf < 8; nf++) {
            int col = hw0 + wn*64 + nf*8 + 2*(lane & 3);
            #pragma unroll
            for (int h = 0; h < 2; h++) {
                size_t idx = (((size_t)(bb*CC + rbase + 8*h)) << 14) + col;
                float2 hv = *(float2*)&g_h[idx];
                float v0 = (acc[mf][nf][2*h]     + hv.x + addb[h]) * scl[h] + shf[h];
                float v1 = (acc[mf][nf][2*h + 1] + hv.y + addb[h]) * scl[h] + shf[h];
                *(float2*)&g_h[idx] = make_float2(v0, v1);
                lsum  += v0 + v1;
                lsum2 += v0*v0 + v1*v1;
            }
        }
    }
    #pragma unroll
    for (int off = 16; off; off >>= 1) {
        lsum  += __shfl_xor_sync(0xffffffffu, lsum, off);
        lsum2 += __shfl_xor_sync(0xffffffffu, lsum2, off);
    }
    if (lane == 0) {
        int g = (o0 + wm*32) >> 5;
        atomicAdd(&g_stats[(bb*NG + g)*2],     lsum);
        atomicAdd(&g_stats[(bb*NG + g)*2 + 1], lsum2);
    }
}

// ---------------- kH: stats finalize inline + normalize + GELU + residual ----------------
__device__ __forceinline__ float gelu_res(float h, float xr, float ga, float be) {
    float hn = fmaf(h, ga, be);
    return xr + 0.5f*hn*(1.f + erff(hn*0.70710678118654752f));
}

__global__ void __launch_bounds__(256) kH_final(const float* __restrict__ x,
                                                const float* __restrict__ gn_g,
                                                const float* __restrict__ gn_b,
                                                float* __restrict__ out) {
    int idx4 = blockIdx.x*256 + threadIdx.x;
    int base = idx4 << 2;
    int c = (base >> 14) & 255;
    int b = base >> 22;
    int g = c >> 5;
    float s  = g_stats[(b*NG + g)*2];
    float s2 = g_stats[(b*NG + g)*2 + 1];
    const float inv = 1.f / 524288.f;
    float mu = s * inv;
    float rs = rsqrtf(fmaxf(s2 * inv - mu*mu, 0.f) + EPSV);
    float ga = gn_g[c] * rs;
    float be = gn_b[c] - mu * ga;
    float4 hv = ((const float4*)g_h)[idx4];
    float4 xv = ((const float4*)x)[idx4];
    float4 r;
    r.x = gelu_res(hv.x, xv.x, ga, be);
    r.y = gelu_res(hv.y, xv.y, ga, be);
    r.z = gelu_res(hv.z, xv.z, ga, be);
    r.w = gelu_res(hv.w, xv.w, ga, be);
    ((float4*)out)[idx4] = r;
}

extern "C" void kernel_launch(void* const* d_in, const int* in_sizes, int n_in,
                              void* d_out, int out_size) {
    const float* x        = (const float*)d_in[0];
    const float* t_emb    = (const float*)d_in[1];
    const float* cond_emb = (const float*)d_in[2];
    const float* w_real   = (const float*)d_in[3];
    const float* w_imag   = (const float*)d_in[4];
    const float* pw_w     = (const float*)d_in[5];
    const float* pw_b     = (const float*)d_in[6];
    const float* tp_w     = (const float*)d_in[7];
    const float* tp_b     = (const float*)d_in[8];
    const float* cp_w     = (const float*)d_in[9];
    const float* cp_b     = (const float*)d_in[10];
    const float* gn_g     = (const float*)d_in[11];
    const float* gn_b     = (const float*)d_in[12];
    float* out = (float*)d_out;

    static int smem_set = 0;
    if (!smem_set) {
        cudaFuncSetAttribute(kF_mma, cudaFuncAttributeMaxDynamicSharedMemorySize, 73728);
        cudaFuncSetAttribute(kAB_fused, cudaFuncAttributeMaxDynamicSharedMemorySize, 107008);
        cudaFuncSetAttribute(kC_mix6, cudaFuncAttributeMaxDynamicSharedMemorySize, 49152);
        cudaFuncSetAttribute(kDE_fused, cudaFuncAttributeMaxDynamicSharedMemorySize, 68608);
        smem_set = 1;
    }

    k0_prep<<<129, 256>>>(t_emb, cond_emb, tp_w, tp_b, cp_w, cp_b);
    kAB_fused<<<4096, 256, 107008>>>(x);
    kC_mix6<<<1024, 256, 49152>>>(w_real, w_imag);
    kDE_fused<<<8192, 256, 68608>>>();
    kF_mma<<<4096, 256, 73728>>>(x, pw_w, pw_b);
    kH_final<<<65536, 256>>>(x, gn_g, gn_b, out);
}

// round 17
// speedup vs baseline: 1.0605x; 1.0605x over previous
#include <cuda_runtime.h>
#include <cstdint>
#include <math.h>

#define BB 16
#define CC 256
#define HH 128
#define WW 128
#define HW 16384
#define MM 32
#define NMODE 1024
#define TD 512
#define CD 512
#define NG 8
#define EPSV 1e-5f

typedef unsigned long long u64;

// ---------------- persistent scratch ----------------
__device__ float2 g_A[(size_t)BB*CC*HH*MM];      // reused as kC half-1 output
__device__ float2 g_Smode[(size_t)BB*CC*NMODE];  // SoA per kx: 64 floats = 16 groups (r,r,i,i)
__device__ float2 g_Omode[(size_t)BB*CC*NMODE];  // kC half-0 output
__device__ float  g_h[(size_t)BB*CC*HW];
__device__ float  g_tvec[BB*CC];
__device__ float  g_scale[BB*CC];
__device__ float  g_shift[BB*CC];
__device__ float  g_stats[BB*NG*2];
__device__ float2 g_tabJK[HH*MM];
__device__ float2 g_tabKJ[MM*HH];

// ---------------- helpers ----------------
__device__ __forceinline__ uint32_t smem_u32(const void* p) {
    return (uint32_t)__cvta_generic_to_shared(p);
}
__device__ __forceinline__ void cpasync16(uint32_t dst, const void* src) {
    asm volatile("cp.async.ca.shared.global [%0], [%1], 16;" :: "r"(dst), "l"(src));
}
__device__ __forceinline__ void cpasync16cg(uint32_t dst, const void* src) {
    asm volatile("cp.async.cg.shared.global [%0], [%1], 16;" :: "r"(dst), "l"(src));
}
__device__ __forceinline__ void cpcommit() { asm volatile("cp.async.commit_group;"); }
template<int N>
__device__ __forceinline__ void cpwait() { asm volatile("cp.async.wait_group %0;" :: "n"(N)); }
__device__ __forceinline__ uint32_t f2tf(float v) { return __float_as_uint(v); }
__device__ __forceinline__ float tf32r(float v) {
    uint32_t r;
    asm("cvt.rna.tf32.f32 %0, %1;" : "=r"(r) : "f"(v));
    return __uint_as_float(r);
}
__device__ __forceinline__ void mma_tf32(float* d, const uint32_t* a, const uint32_t* b) {
    asm volatile("mma.sync.aligned.m16n8k8.row.col.f32.tf32.tf32.f32 "
                 "{%0,%1,%2,%3}, {%4,%5,%6,%7}, {%8,%9}, {%0,%1,%2,%3};"
                 : "+f"(d[0]), "+f"(d[1]), "+f"(d[2]), "+f"(d[3])
                 : "r"(a[0]), "r"(a[1]), "r"(a[2]), "r"(a[3]), "r"(b[0]), "r"(b[1]));
}
__device__ __forceinline__ u64 pack2(float x, float y) {
    u64 r; asm("mov.b64 %0, {%1, %2};" : "=l"(r) : "f"(x), "f"(y)); return r;
}
__device__ __forceinline__ u64 fma2(u64 a, u64 b, u64 c) {
    u64 d; asm("fma.rn.f32x2 %0, %1, %2, %3;" : "=l"(d) : "l"(a), "l"(b), "l"(c)); return d;
}
__device__ __forceinline__ u64 neg2(u64 a) { return a ^ 0x8000000080000000ULL; }
__device__ __forceinline__ float2 unpack2(u64 a) {
    float2 v; asm("mov.b64 {%0, %1}, %2;" : "=f"(v.x), "=f"(v.y) : "l"(a)); return v;
}

// ---------------- K0: tables + embedding projections (parallelized) ----------------
__global__ void k0_prep(const float* __restrict__ t_emb, const float* __restrict__ cond_emb,
                        const float* __restrict__ tp_w, const float* __restrict__ tp_b,
                        const float* __restrict__ cp_w, const float* __restrict__ cp_b) {
    int t = threadIdx.x;
    if (blockIdx.x == 128) {
        for (int e = t; e < HH*MM; e += 256) {
            int j = e >> 5, k = e & 31;
            float ang = (float)((j * k) & 127) * 0.049087385212340517f;
            float s, c; sincosf(ang, &s, &c);
            g_tabJK[j*MM + k] = make_float2(c, s);
            g_tabKJ[k*HH + j] = make_float2(c, s);
        }
        if (t < BB*NG*2) g_stats[t] = 0.f;
        return;
    }
    int b = blockIdx.x >> 3;
    int cg = blockIdx.x & 7;
    __shared__ float st[TD];
    __shared__ float sc[CD];
    __shared__ float red[3][32][9];
    for (int e = t; e < TD; e += 256) { float v = t_emb[b*TD + e];   st[e] = v / (1.f + expf(-v)); }
    for (int e = t; e < CD; e += 256) { float v = cond_emb[b*CD + e]; sc[e] = v / (1.f + expf(-v)); }
    __syncthreads();
    int cl = t & 31, sl = t >> 5;
    int c = cg*32 + cl;
    float tv = 0.f, s1 = 0.f, s2 = 0.f;
    const float* tw = tp_w + (size_t)c*TD + sl*64;
    const float* c1 = cp_w + (size_t)c*CD + sl*64;
    const float* c2 = cp_w + (size_t)(c + CC)*CD + sl*64;
    #pragma unroll 4
    for (int d = 0; d < 64; d++) tv = fmaf(st[sl*64 + d], tw[d], tv);
    #pragma unroll 4
    for (int d = 0; d < 64; d++) { s1 = fmaf(sc[sl*64 + d], c1[d], s1); s2 = fmaf(sc[sl*64 + d], c2[d], s2); }
    red[0][cl][sl] = tv; red[1][cl][sl] = s1; red[2][cl][sl] = s2;
    __syncthreads();
    if (t < 32) {
        float a0 = 0.f, a1 = 0.f, a2 = 0.f;
        #pragma unroll
        for (int s = 0; s < 8; s++) { a0 += red[0][t][s]; a1 += red[1][t][s]; a2 += red[2][t][s]; }
        int cc = cg*32 + t;
        g_tvec[b*CC + cc]  = a0 + tp_b[cc];
        g_scale[b*CC + cc] = a1 + cp_b[cc];
        g_shift[b*CC + cc] = a2 + cp_b[cc + CC];
    }
}

// ---------------- kAB: fused forward DFT, BOTH phases as tf32 mma ----------------
#define TSA_(k,n)      sdyn[(k)*68 + (n)]
#define XSA_(st,r,k)   sdyn[8704 + (st)*4608 + (r)*36 + (k)]
#define AT2_(ky,c)     sdyn[(ky)*260 + (c)]
#define TB2_(k,c)      sdyn[8320 + (k)*72 + (c)]

__global__ void __launch_bounds__(256, 2) kAB_fused(const float* __restrict__ x) {
    extern __shared__ float sdyn[];
    int t = threadIdx.x, lane = t & 31, warp = t >> 5;
    int wm = warp >> 1, wn = warp & 1;
    int bc = blockIdx.x;
    int R0 = bc * 128;

    for (int e = t; e < HH*MM; e += 256) {
        int m = e >> 5, ky = e & 31;
        float2 cs = g_tabJK[e];
        TSA_(m, 2*ky)     = cs.x;
        TSA_(m, 2*ky + 1) = -cs.y;
    }
    #pragma unroll
    for (int q = 0; q < 4; q++) {
        int idx = t + 256*q;
        int row = idx >> 3, c4 = idx & 7;
        cpasync16(smem_u32(&XSA_(0, row, c4*4)), x + (size_t)(R0 + row)*128 + c4*4);
    }
    cpcommit();

    float acc[2][4][4];
    #pragma unroll
    for (int mf = 0; mf < 2; mf++)
        #pragma unroll
        for (int nf = 0; nf < 4; nf++)
            #pragma unroll
            for (int e = 0; e < 4; e++) acc[mf][nf][e] = 0.f;

    for (int kc = 0; kc < 4; kc++) {
        if (kc + 1 < 4) {
            int k0 = (kc + 1) * 32, st2 = (kc + 1) & 1;
            #pragma unroll
            for (int q = 0; q < 4; q++) {
                int idx = t + 256*q;
                int row = idx >> 3, c4 = idx & 7;
                cpasync16(smem_u32(&XSA_(st2, row, c4*4)), x + (size_t)(R0 + row)*128 + k0 + c4*4);
            }
            cpcommit();
            cpwait<1>();
        } else {
            cpwait<0>();
        }
        __syncthreads();
        int st = kc & 1;
        #pragma unroll
        for (int k8 = 0; k8 < 4; k8++) {
            uint32_t a[2][4], b[4][2];
            int arow = wm*32 + (lane >> 2);
            int acol = (lane & 3) + k8*8;
            #pragma unroll
            for (int mf = 0; mf < 2; mf++) {
                int r = arow + mf*16;
                a[mf][0] = f2tf(XSA_(st, r,     acol));
                a[mf][1] = f2tf(XSA_(st, r + 8, acol));
                a[mf][2] = f2tf(XSA_(st, r,     acol + 4));
                a[mf][3] = f2tf(XSA_(st, r + 8, acol + 4));
            }
            int kg = kc*32 + k8*8 + (lane & 3);
            int bn0 = wn*32 + (lane >> 2);
            #pragma unroll
            for (int nf = 0; nf < 4; nf++) {
                b[nf][0] = f2tf(TSA_(kg,     bn0 + nf*8));
                b[nf][1] = f2tf(TSA_(kg + 4, bn0 + nf*8));
            }
            #pragma unroll
            for (int mf = 0; mf < 2; mf++)
                #pragma unroll
                for (int nf = 0; nf < 4; nf++)
                    mma_tf32(acc[mf][nf], a[mf], b[nf]);
        }
        __syncthreads();
    }

    #pragma unroll
    for (int mf = 0; mf < 2; mf++) {
        int r = wm*32 + mf*16 + (lane >> 2);
        #pragma unroll
        for (int nf = 0; nf < 4; nf++) {
            int ky = wn*16 + nf*4 + (lane & 3);
            *(float2*)&AT2_(ky, 2*r)       = make_float2(acc[mf][nf][0], acc[mf][nf][1]);
            *(float2*)&AT2_(ky, 2*(r + 8)) = make_float2(acc[mf][nf][2], acc[mf][nf][3]);
        }
    }
    for (int e = t; e < 16384; e += 256) {
        int row = e >> 6, colc = e & 63;
        int n = row >> 1, u = row & 1;
        int kx = colc >> 1, v = colc & 1;
        float2 cs = g_tabJK[n*32 + kx];
        float val = u ? (v ? cs.x : cs.y) : (v ? -cs.y : cs.x);
        TB2_(row, colc) = val * (1.f/128.f);
    }
    __syncthreads();

    {
        int wm2 = warp >> 2, wn2 = warp & 3;
        float acc2[2][4];
        #pragma unroll
        for (int nf = 0; nf < 2; nf++)
            #pragma unroll
            for (int e = 0; e < 4; e++) acc2[nf][e] = 0.f;

        int r2 = wm2*16 + (lane >> 2);
        int n2 = wn2*16 + (lane >> 2);
        #pragma unroll
        for (int k8 = 0; k8 < 32; k8++) {
            uint32_t a[4], b[2][2];
            int kk = (lane & 3) + k8*8;
            a[0] = f2tf(AT2_(r2,     kk));
            a[1] = f2tf(AT2_(r2 + 8, kk));
            a[2] = f2tf(AT2_(r2,     kk + 4));
            a[3] = f2tf(AT2_(r2 + 8, kk + 4));
            #pragma unroll
            for (int nf = 0; nf < 2; nf++) {
                b[nf][0] = f2tf(TB2_(kk,     n2 + nf*8));
                b[nf][1] = f2tf(TB2_(kk + 4, n2 + nf*8));
            }
            #pragma unroll
            for (int nf = 0; nf < 2; nf++)
                mma_tf32(acc2[nf], a, b[nf]);
        }

        float* So = (float*)g_Smode + (size_t)bc*2048;
        int ky0 = r2, ky1 = r2 + 8;
        int off0 = (ky0 >> 1)*4 + (ky0 & 1);
        int off1 = (ky1 >> 1)*4 + (ky1 & 1);
        #pragma unroll
        for (int nf = 0; nf < 2; nf++) {
            int kx = wn2*8 + (lane & 3) + nf*4;
            float* dst = So + kx*64;
            dst[off0]     = acc2[nf][0];
            dst[off0 + 2] = acc2[nf][1];
            dst[off1]     = acc2[nf][2];
            dst[off1 + 2] = acc2[nf][3];
        }
    }
}

// ---------------- kC: channel mix, split-K 2, 6-stage pipeline; W loads bypass L1 (.cg) ----------------
#define SS6(st,b,f)    sdyn[(st) + (b)*64 + (f)]
#define WS6(st,h,o,f)  sdyn[6144 + (st) + (h)*512 + (o)*32 + (f)]

__global__ void __launch_bounds__(256, 2) kC_mix6(const float* __restrict__ w_real,
                                                  const float* __restrict__ w_imag) {
    extern __shared__ float sdyn[];
    int t = threadIdx.x;
    int ih = blockIdx.x >> 9;
    int kx = (blockIdx.x >> 4) & 31;
    int o0 = (blockIdx.x & 15) << 4;
    int i0 = ih << 7;
    const int NI = 128;

    int sb = t >> 4, sf = t & 15;
    const float* wsrc = (t < 128) ? w_real : w_imag;
    int whalf = t >> 7, wo = (t >> 3) & 15, wf = t & 7;

    int kyp = t & 15, bq = (t >> 4) & 3, oq = t >> 6;

    u64 ar[4][4], ai[4][4];
    #pragma unroll
    for (int b4 = 0; b4 < 4; b4++)
        #pragma unroll
        for (int o4 = 0; o4 < 4; o4++) { ar[b4][o4] = 0ULL; ai[b4][o4] = 0ULL; }

    const float* sPtr = (const float*)g_Smode + (size_t)(sb*CC + i0)*2048 + kx*64 + sf*4;
    const float* wPtr = wsrc + ((size_t)(i0*CC + o0 + wo) << 10) + (kx << 5) + wf*4;
    uint32_t sDst = smem_u32(&SS6(0, sb, sf*4));
    uint32_t wDst = smem_u32(&WS6(0, whalf, wo, wf*4));

    #pragma unroll
    for (int i = 0; i < 5; i++) {
        cpasync16(sDst + i*4096, sPtr);  sPtr += 2048;
        cpasync16cg(wDst + i*4096, wPtr);  wPtr += (size_t)CC << 10;
        cpcommit();
    }

    int stc = 0;
    int stp = 5*1024;
    uint32_t sPD = sDst + 5*4096, wPD = wDst + 5*4096;

    for (int i = 0; i < NI; i++) {
        cpwait<4>();
        __syncthreads();
        if (i + 5 < NI) {
            cpasync16(sPD, sPtr);  sPtr += 2048;
            cpasync16cg(wPD, wPtr);  wPtr += (size_t)CC << 10;
        }
        cpcommit();
        sPD += 4096; wPD += 4096;
        if (stp == 5*1024) { sPD -= 6*4096; wPD -= 6*4096; stp = 0; } else stp += 1024;

        int st = stc;
        u64 sx[4], sy[4], nsy[4];
        #pragma unroll
        for (int b4 = 0; b4 < 4; b4++) {
            int b = 4*b4 + bq;
            sx[b4]  = *(u64*)&SS6(st, b, 4*kyp);
            sy[b4]  = *(u64*)&SS6(st, b, 4*kyp + 2);
            nsy[b4] = neg2(sy[b4]);
        }
        #pragma unroll
        for (int o4 = 0; o4 < 4; o4++) {
            int ow = 4*o4 + oq;
            u64 wr = *(u64*)&WS6(st, 0, ow, 2*kyp);
            u64 wi = *(u64*)&WS6(st, 1, ow, 2*kyp);
            #pragma unroll
            for (int b4 = 0; b4 < 4; b4++) {
                ar[b4][o4] = fma2(sx[b4], wr, fma2(nsy[b4], wi, ar[b4][o4]));
                ai[b4][o4] = fma2(sx[b4], wi, fma2(sy[b4],  wr, ai[b4][o4]));
            }
        }
        stc = (stc == 5*1024) ? 0 : stc + 1024;
    }
    float* OmF = ih ? (float*)g_A : (float*)g_Omode;
    #pragma unroll
    for (int b4 = 0; b4 < 4; b4++) {
        int b = 4*b4 + bq;
        #pragma unroll
        for (int o4 = 0; o4 < 4; o4++) {
            int o = o0 + 4*o4 + oq;
            float* dst = OmF + (size_t)(b*CC + o)*2048 + kx*64;
            *(float2*)&dst[2*kyp]      = unpack2(ar[b4][o4]);
            *(float2*)&dst[32 + 2*kyp] = unpack2(ai[b4][o4]);
        }
    }
}

// ---------------- kDE: both inverse DFTs as tf32 mma; merges split-K halves ----------------
#define GSE_(r,k)   sdyn[(r)*68 + (k)]
#define USE_(k,n)   sdyn[8704 + (k)*132 + (n)]
#define B1_(k,c)    sdyn[17152 + (k)*68 + (c)]

__global__ void __launch_bounds__(256, 2) kDE_fused() {
    extern __shared__ float sdyn[];
    int t = threadIdx.x, lane = t & 31, warp = t >> 5;
    int wm = warp >> 1, wn = warp & 1;
    int bo = blockIdx.x;

    for (int e = t; e < MM*HH; e += 256) {
        int ky = e >> 7, m = e & 127;
        float2 cs = g_tabKJ[e];
        USE_(2*ky,     m) = cs.x;
        USE_(2*ky + 1, m) = -cs.y;
    }
    {
        int kx = t >> 3, g = t & 7;
        const float* s1 = (const float*)g_Omode + (size_t)bo*2048 + kx*64;
        const float* s2 = (const float*)g_A + (size_t)bo*2048 + kx*64;
        float4 or1 = *(const float4*)&s1[g*4];
        float4 or2 = *(const float4*)&s2[g*4];
        float4 oi1 = *(const float4*)&s1[32 + g*4];
        float4 oi2 = *(const float4*)&s2[32 + g*4];
        float Or[4] = {or1.x + or2.x, or1.y + or2.y, or1.z + or2.z, or1.w + or2.w};
        float Oi[4] = {oi1.x + oi2.x, oi1.y + oi2.y, oi1.z + oi2.z, oi1.w + oi2.w};
        #pragma unroll
        for (int j = 0; j < 4; j++) {
            int ky = g*4 + j;
            float fac = (ky == 0 ? 1.f : 2.f) * (1.f/128.f);
            float fr = tf32r(Or[j]*fac), fi = tf32r(Oi[j]*fac);
            *(float2*)&B1_(2*kx,     2*ky) = make_float2(fr, fi);
            *(float2*)&B1_(2*kx + 1, 2*ky) = make_float2(fi, -fr);
        }
    }
    __syncthreads();

    {
        float acc1[2][4][4];
        #pragma unroll
        for (int mf = 0; mf < 2; mf++)
            #pragma unroll
            for (int nf = 0; nf < 4; nf++)
                #pragma unroll
                for (int e = 0; e < 4; e++) acc1[mf][nf][e] = 0.f;

        #pragma unroll
        for (int k8 = 0; k8 < 8; k8++) {
            uint32_t a[2][4], b[4][2];
            int k = (lane & 3) + k8*8;
            #pragma unroll
            for (int mf = 0; mf < 2; mf++) {
                int r = wm*32 + mf*16 + (lane >> 2);
                a[mf][0] = f2tf(USE_(k,     r));
                a[mf][1] = f2tf(USE_(k,     r + 8));
                a[mf][2] = f2tf(USE_(k + 4, r));
                a[mf][3] = f2tf(USE_(k + 4, r + 8));
            }
            int col0 = wn*32 + (lane >> 2);
            #pragma unroll
            for (int nf = 0; nf < 4; nf++) {
                b[nf][0] = f2tf(B1_(k,     col0 + nf*8));
                b[nf][1] = f2tf(B1_(k + 4, col0 + nf*8));
            }
            #pragma unroll
            for (int mf = 0; mf < 2; mf++)
                #pragma unroll
                for (int nf = 0; nf < 4; nf++)
                    mma_tf32(acc1[mf][nf], a[mf], b[nf]);
        }
        __syncthreads();
        #pragma unroll
        for (int mf = 0; mf < 2; mf++) {
            int r = wm*32 + mf*16 + (lane >> 2);
            #pragma unroll
            for (int nf = 0; nf < 4; nf++) {
                int col = wn*32 + nf*8 + 2*(lane & 3);
                *(float2*)&GSE_(r,     col) = make_float2(acc1[mf][nf][0], acc1[mf][nf][1]);
                *(float2*)&GSE_(r + 8, col) = make_float2(acc1[mf][nf][2], acc1[mf][nf][3]);
            }
        }
    }
    __syncthreads();

    float acc[2][8][4];
    #pragma unroll
    for (int mf = 0; mf < 2; mf++)
        #pragma unroll
        for (int nf = 0; nf < 8; nf++)
            #pragma unroll
            for (int e = 0; e < 4; e++) acc[mf][nf][e] = 0.f;

    #pragma unroll
    for (int k8 = 0; k8 < 8; k8++) {
        uint32_t a[2][4], b[8][2];
        int arow = wm*32 + (lane >> 2);
        int acol = (lane & 3) + k8*8;
        #pragma unroll
        for (int mf = 0; mf < 2; mf++) {
            int r = arow + mf*16;
            a[mf][0] = f2tf(GSE_(r,     acol));
            a[mf][1] = f2tf(GSE_(r + 8, acol));
            a[mf][2] = f2tf(GSE_(r,     acol + 4));
            a[mf][3] = f2tf(GSE_(r + 8, acol + 4));
        }
        int kg = k8*8 + (lane & 3);
        int bn0 = wn*64 + (lane >> 2);
        #pragma unroll
        for (int nf = 0; nf < 8; nf++) {
            b[nf][0] = f2tf(USE_(kg,     bn0 + nf*8));
            b[nf][1] = f2tf(USE_(kg + 4, bn0 + nf*8));
        }
        #pragma unroll
        for (int mf = 0; mf < 2; mf++)
            #pragma unroll
            for (int nf = 0; nf < 8; nf++)
                mma_tf32(acc[mf][nf], a[mf], b[nf]);
    }

    #pragma unroll
    for (int mf = 0; mf < 2; mf++) {
        int r = bo*128 + wm*32 + mf*16 + (lane >> 2);
        #pragma unroll
        for (int nf = 0; nf < 8; nf++) {
            int col = wn*64 + nf*8 + 2*(lane & 3);
            *(float2*)&g_h[(size_t)r*128 + col]       = make_float2(acc[mf][nf][0], acc[mf][nf][1]);
            *(float2*)&g_h[(size_t)(r + 8)*128 + col] = make_float2(acc[mf][nf][2], acc[mf][nf][3]);
        }
    }
}

// ---------------- kF: pointwise GEMM via tf32 mma + fused epilogue + GN stats ----------------
#define ASM_(st,r,c) sdyn[(st)*4608 + (r)*36 + (c)]
#define BSM_(st,k,n) sdyn[9216 + (st)*4352 + (k)*136 + (n)]

__global__ void __launch_bounds__(256, 2) kF_mma(const float* __restrict__ x,
                                                 const float* __restrict__ pw_w,
                                                 const float* __restrict__ pw_b) {
    extern __shared__ float sdyn[];
    int t = threadIdx.x;
    int lane = t & 31, warp = t >> 5;
    int wm = warp >> 1, wn = warp & 1;
    int bi = blockIdx.x;
    int bb = bi >> 8;
    int ot = (bi >> 7) & 1, hwt = bi & 127;
    int o0 = ot * 128, hw0 = hwt * 128;

    float acc[2][8][4];
    #pragma unroll
    for (int mf = 0; mf < 2; mf++)
        #pragma unroll
        for (int nf = 0; nf < 8; nf++)
            #pragma unroll
            for (int e = 0; e < 4; e++) acc[mf][nf][e] = 0.f;

    {
        int i0 = 0;
        #pragma unroll
        for (int q = 0; q < 4; q++) {
            int idx = t + 256*q;
            int row = idx >> 3, c4 = idx & 7;
            cpasync16(smem_u32(&ASM_(0, row, c4*4)), pw_w + (size_t)(o0 + row)*CC + i0 + c4*4);
        }
        #pragma unroll
        for (int q = 0; q < 4; q++) {
            int idx = t + 256*q;
            int row = idx >> 5, c4 = idx & 31;
            cpasync16(smem_u32(&BSM_(0, row, c4*4)),
                      x + (((size_t)(bb*CC + i0 + row)) << 14) + hw0 + c4*4);
        }
        cpcommit();
    }

    for (int kc = 0; kc < 8; kc++) {
        if (kc + 1 < 8) {
            int i0 = (kc + 1) * 32, st2 = (kc + 1) & 1;
            #pragma unroll
            for (int q = 0; q < 4; q++) {
                int idx = t + 256*q;
                int row = idx >> 3, c4 = idx & 7;
                cpasync16(smem_u32(&ASM_(st2, row, c4*4)), pw_w + (size_t)(o0 + row)*CC + i0 + c4*4);
            }
            #pragma unroll
            for (int q = 0; q < 4; q++) {
                int idx = t + 256*q;
                int row = idx >> 5, c4 = idx & 31;
                cpasync16(smem_u32(&BSM_(st2, row, c4*4)),
                          x + (((size_t)(bb*CC + i0 + row)) << 14) + hw0 + c4*4);
            }
            cpcommit();
            cpwait<1>();
        } else {
            cpwait<0>();
        }
        __syncthreads();
        int st = kc & 1;
        #pragma unroll
        for (int k8 = 0; k8 < 4; k8++) {
            uint32_t a[2][4], b[8][2];
            int arow = wm*32 + (lane >> 2);
            int acol = (lane & 3) + k8*8;
            #pragma unroll
            for (int mf = 0; mf < 2; mf++) {
                int r = arow + mf*16;
                a[mf][0] = f2tf(ASM_(st, r,     acol));
                a[mf][1] = f2tf(ASM_(st, r + 8, acol));
                a[mf][2] = f2tf(ASM_(st, r,     acol + 4));
                a[mf][3] = f2tf(ASM_(st, r + 8, acol + 4));
            }
            int bk = (lane & 3) + k8*8;
            int bn0 = wn*64 + (lane >> 2);
            #pragma unroll
            for (int nf = 0; nf < 8; nf++) {
                b[nf][0] = f2tf(BSM_(st, bk,     bn0 + nf*8));
                b[nf][1] = f2tf(BSM_(st, bk + 4, bn0 + nf*8));
            }
            #pragma unroll
            for (int mf = 0; mf < 2; mf++)
                #pragma unroll
                for (int nf = 0; nf < 8; nf++)
                    mma_tf32(acc[mf][nf], a[mf], b[nf]);
        }
        __syncthreads();
    }

    float lsum = 0.f, lsum2 = 0.f;
    #pragma unroll
    for (int mf = 0; mf < 2; mf++) {
        int rbase = o0 + wm*32 + mf*16 + (lane >> 2);
        float addb[2], scl[2], shf[2];
        #pragma unroll
        for (int h = 0; h < 2; h++) {
            int o = rbase + 8*h;
            addb[h] = pw_b[o] + g_tvec[bb*CC + o];
            scl[h]  = 1.f + g_scale[bb*CC + o];
            shf[h]  = g_shift[bb*CC + o];
        }
        #pragma unroll
        for (int nf = 0; nf < 8; nf++) {
            int col = hw0 + wn*64 + nf*8 + 2*(lane & 3);
            #pragma unroll
            for (int h = 0; h < 2; h++) {
                size_t idx = (((size_t)(bb*CC + rbase + 8*h)) << 14) + col;
                float2 hv = *(float2*)&g_h[idx];
                float v0 = (acc[mf][nf][2*h]     + hv.x + addb[h]) * scl[h] + shf[h];
                float v1 = (acc[mf][nf][2*h + 1] + hv.y + addb[h]) * scl[h] + shf[h];
                *(float2*)&g_h[idx] = make_float2(v0, v1);
                lsum  += v0 + v1;
                lsum2 += v0*v0 + v1*v1;
            }
        }
    }
    #pragma unroll
    for (int off = 16; off; off >>= 1) {
        lsum  += __shfl_xor_sync(0xffffffffu, lsum, off);
        lsum2 += __shfl_xor_sync(0xffffffffu, lsum2, off);
    }
    if (lane == 0) {
        int g = (o0 + wm*32) >> 5;
        atomicAdd(&g_stats[(bb*NG + g)*2],     lsum);
        atomicAdd(&g_stats[(bb*NG + g)*2 + 1], lsum2);
    }
}

// ---------------- kH: stats finalize inline + normalize + GELU + residual ----------------
__device__ __forceinline__ float gelu_res(float h, float xr, float ga, float be) {
    float hn = fmaf(h, ga, be);
    return xr + 0.5f*hn*(1.f + erff(hn*0.70710678118654752f));
}

__global__ void __launch_bounds__(256) kH_final(const float* __restrict__ x,
                                                const float* __restrict__ gn_g,
                                                const float* __restrict__ gn_b,
                                                float* __restrict__ out) {
    int idx4 = blockIdx.x*256 + threadIdx.x;
    int base = idx4 << 2;
    int c = (base >> 14) & 255;
    int b = base >> 22;
    int g = c >> 5;
    float s  = g_stats[(b*NG + g)*2];
    float s2 = g_stats[(b*NG + g)*2 + 1];
    const float inv = 1.f / 524288.f;
    float mu = s * inv;
    float rs = rsqrtf(fmaxf(s2 * inv - mu*mu, 0.f) + EPSV);
    float ga = gn_g[c] * rs;
    float be = gn_b[c] - mu * ga;
    float4 hv = ((const float4*)g_h)[idx4];
    float4 xv = ((const float4*)x)[idx4];
    float4 r;
    r.x = gelu_res(hv.x, xv.x, ga, be);
    r.y = gelu_res(hv.y, xv.y, ga, be);
    r.z = gelu_res(hv.z, xv.z, ga, be);
    r.w = gelu_res(hv.w, xv.w, ga, be);
    ((float4*)out)[idx4] = r;
}

extern "C" void kernel_launch(void* const* d_in, const int* in_sizes, int n_in,
                              void* d_out, int out_size) {
    const float* x        = (const float*)d_in[0];
    const float* t_emb    = (const float*)d_in[1];
    const float* cond_emb = (const float*)d_in[2];
    const float* w_real   = (const float*)d_in[3];
    const float* w_imag   = (const float*)d_in[4];
    const float* pw_w     = (const float*)d_in[5];
    const float* pw_b     = (const float*)d_in[6];
    const float* tp_w     = (const float*)d_in[7];
    const float* tp_b     = (const float*)d_in[8];
    const float* cp_w     = (const float*)d_in[9];
    const float* cp_b     = (const float*)d_in[10];
    const float* gn_g     = (const float*)d_in[11];
    const float* gn_b     = (const float*)d_in[12];
    float* out = (float*)d_out;

    static int smem_set = 0;
    if (!smem_set) {
        cudaFuncSetAttribute(kF_mma, cudaFuncAttributeMaxDynamicSharedMemorySize, 73728);
        cudaFuncSetAttribute(kAB_fused, cudaFuncAttributeMaxDynamicSharedMemorySize, 107008);
        cudaFuncSetAttribute(kC_mix6, cudaFuncAttributeMaxDynamicSharedMemorySize, 49152);
        cudaFuncSetAttribute(kDE_fused, cudaFuncAttributeMaxDynamicSharedMemorySize, 86016);
        smem_set = 1;
    }

    k0_prep<<<129, 256>>>(t_emb, cond_emb, tp_w, tp_b, cp_w, cp_b);
    kAB_fused<<<4096, 256, 107008>>>(x);
    kC_mix6<<<1024, 256, 49152>>>(w_real, w_imag);
    kDE_fused<<<4096, 256, 86016>>>();
    kF_mma<<<4096, 256, 73728>>>(x, pw_w, pw_b);
    kH_final<<<65536, 256>>>(x, gn_g, gn_b, out);
}